// round 4
// baseline (speedup 1.0000x reference)
#include <cuda_runtime.h>
#include <cuda_bf16.h>
#include <cstdint>

#define PLANES 80
#define FLAT   5120      // 80 * 64
#define NMOVES 1858
#define BATCH  16384
#define ROW_BYTES (FLAT * 4)   // 20480

// move -> flat-index map, rebuilt every launch (deterministic per call).
__device__ __align__(16) int g_idx[NMOVES];

// ---------------------------------------------------------------------------
// PTX helpers
// ---------------------------------------------------------------------------
__device__ __forceinline__ uint32_t smem_u32(const void* p) {
    uint32_t a;
    asm("{ .reg .u64 t; cvta.to.shared.u64 t, %1; cvt.u32.u64 %0, t; }"
        : "=r"(a) : "l"(p));
    return a;
}

__device__ __forceinline__ void mbar_init(uint32_t addr, uint32_t count) {
    asm volatile("mbarrier.init.shared.b64 [%0], %1;" :: "r"(addr), "r"(count) : "memory");
}

__device__ __forceinline__ void mbar_expect_tx(uint32_t addr, uint32_t bytes) {
    asm volatile("mbarrier.arrive.expect_tx.shared.b64 _, [%0], %1;"
                 :: "r"(addr), "r"(bytes) : "memory");
}

__device__ __forceinline__ void bulk_g2s(uint32_t dst_smem, const void* gsrc,
                                         uint32_t bytes, uint32_t mbar) {
    asm volatile(
        "cp.async.bulk.shared::cta.global.mbarrier::complete_tx::bytes "
        "[%0], [%1], %2, [%3];"
        :: "r"(dst_smem), "l"(gsrc), "r"(bytes), "r"(mbar) : "memory");
}

__device__ __forceinline__ void mbar_wait(uint32_t addr, uint32_t phase) {
    asm volatile(
        "{\n\t"
        ".reg .pred P;\n\t"
        "W%=:\n\t"
        "mbarrier.try_wait.parity.acquire.cta.shared::cta.b64 P, [%0], %1, 0x989680;\n\t"
        "@!P bra W%=;\n\t"
        "}"
        :: "r"(addr), "r"(phase) : "memory");
}

// ---------------------------------------------------------------------------
// Kernel A: recover src index per move column from the 0/1 selection matrix.
// Lane-interleaved uint4 loads, MLP=8 per thread. DEFAULT cache policy so fc1
// can stay L2-resident across graph replays (gather streams with .cs/TMA and
// should not evict it).
// ---------------------------------------------------------------------------
__global__ __launch_bounds__(256)
void build_idx_kernel(const uint4* __restrict__ fc1v) {
    const int total4 = FLAT * NMOVES / 4;                 // 2,378,240
    const int warp = (blockIdx.x * 256 + threadIdx.x) >> 5;
    const int lane = threadIdx.x & 31;
    const int base = warp * 256 + lane;                   // float4 index

    #pragma unroll
    for (int j = 0; j < 8; j++) {
        int t = base + j * 32;
        if (t < total4) {
            uint4 v = fc1v[t];
            if (v.x | v.y | v.z | v.w) {   // rare: <=1858 hits in 9.5M elems
                long long e = (long long)t * 4;
                if (v.x) { long long ek = e + 0; g_idx[(int)(ek % NMOVES)] = (int)(ek / NMOVES); }
                if (v.y) { long long ek = e + 1; g_idx[(int)(ek % NMOVES)] = (int)(ek / NMOVES); }
                if (v.z) { long long ek = e + 2; g_idx[(int)(ek % NMOVES)] = (int)(ek / NMOVES); }
                if (v.w) { long long ek = e + 3; g_idx[(int)(ek % NMOVES)] = (int)(ek / NMOVES); }
            }
        }
    }
}

// ---------------------------------------------------------------------------
// Kernel B: out[b, m] = x[b, g_idx[m]].
// Persistent double-buffered CTAs: indices preloaded into registers ONCE per
// block, bulk-copy of row r+stride issued while gathering row r.
// 929 float2 pairs per row: thread t handles pairs t, t+256, t+512, (t+768).
// ---------------------------------------------------------------------------
__global__ __launch_bounds__(256)
void policy_gather_kernel(const float* __restrict__ x,
                          float* __restrict__ out,
                          int nrows) {
    __shared__ __align__(128) float rowbuf[2][FLAT];     // 40 KB
    __shared__ __align__(8) unsigned long long mbar[2];

    const int tid = threadIdx.x;
    const uint32_t mb0 = smem_u32(&mbar[0]);
    const uint32_t mb1 = smem_u32(&mbar[1]);
    const uint32_t rb0 = smem_u32(rowbuf[0]);
    const uint32_t rb1 = smem_u32(rowbuf[1]);

    if (tid == 0) { mbar_init(mb0, 1); mbar_init(mb1, 1); }
    __syncthreads();

    int r = blockIdx.x;
    const int stride = gridDim.x;

    // kick off first copy ASAP
    if (tid == 0 && r < nrows) {
        mbar_expect_tx(mb0, ROW_BYTES);
        bulk_g2s(rb0, x + (size_t)r * FLAT, ROW_BYTES, mb0);
    }

    // preload gather indices into registers (reused for every row)
    const int2* idxp = reinterpret_cast<const int2*>(g_idx);
    const int2 i0 = idxp[tid];
    const int2 i1 = idxp[tid + 256];
    const int2 i2 = idxp[tid + 512];
    const bool has3 = tid < (NMOVES / 2 - 768);          // 161 threads
    const int2 i3 = has3 ? idxp[tid + 768] : make_int2(0, 0);

    int buf = 0, p0 = 0, p1 = 0;
    for (; r < nrows; r += stride) {
        const int rn = r + stride;
        // issue next row's copy into the other buffer (it was fully consumed
        // before the __syncthreads() that ended the previous iteration)
        if (tid == 0 && rn < nrows) {
            const uint32_t mnext = buf ? mb0 : mb1;
            mbar_expect_tx(mnext, ROW_BYTES);
            bulk_g2s(buf ? rb0 : rb1, x + (size_t)rn * FLAT, ROW_BYTES, mnext);
        }
        if (buf) { mbar_wait(mb1, p1); p1 ^= 1; }
        else     { mbar_wait(mb0, p0); p0 ^= 1; }

        const float* rw = rowbuf[buf];
        float2* o = reinterpret_cast<float2*>(out + (size_t)r * NMOVES);
        float2 v;
        v.x = rw[i0.x]; v.y = rw[i0.y]; __stcs(o + tid,       v);
        v.x = rw[i1.x]; v.y = rw[i1.y]; __stcs(o + tid + 256, v);
        v.x = rw[i2.x]; v.y = rw[i2.y]; __stcs(o + tid + 512, v);
        if (has3) {
            v.x = rw[i3.x]; v.y = rw[i3.y]; __stcs(o + tid + 768, v);
        }
        __syncthreads();   // everyone done reading rowbuf[buf] before reuse
        buf ^= 1;
    }
}

extern "C" void kernel_launch(void* const* d_in, const int* in_sizes, int n_in,
                              void* d_out, int out_size) {
    const float* x   = (const float*)d_in[0];   // [16384, 80, 8, 8] fp32
    const float* fc1 = (const float*)d_in[1];   // [5120, 1858] fp32
    float* out = (float*)d_out;                 // [16384, 1858] fp32

    // A: rebuild the selection index (38 MB scan; L2-friendly).
    build_idx_kernel<<<1162, 256>>>(reinterpret_cast<const uint4*>(fc1));

    // B: persistent pipelined gather. 740 blocks ~= 5 CTAs/SM on 148 SMs
    // (40 KB smem per block), one wave.
    policy_gather_kernel<<<740, 256>>>(x, out, BATCH);
}